// round 1
// baseline (speedup 1.0000x reference)
#include <cuda_runtime.h>
#include <stdint.h>

#define NMAX 50000
#define EMAX 800000
#define HID 128
#define FEAT 64

// ---------------- scratch (static device globals; no allocation) ----------------
__device__ float g_xA[(size_t)NMAX * HID];
__device__ float g_xB[(size_t)NMAX * HID];
__device__ float g_agg[(size_t)NMAX * 3 * HID];   // [node][rel][128], pre-scaled by 1/deg
__device__ int   g_counts[NMAX];
__device__ int   g_off[NMAX + 1];
__device__ int   g_cursor[NMAX];
__device__ int   g_csr[EMAX];                      // packed: (src<<2)|etype
__device__ int   g_tcnt[4];
__device__ int   g_tlist[4 * NMAX];
__device__ float g_pooled[HID];

// ---------------- f32x2 packed helpers (Blackwell) ----------------
__device__ __forceinline__ unsigned long long pk2(float lo, float hi) {
    unsigned long long r;
    asm("mov.b64 %0, {%1, %2};" : "=l"(r) : "f"(lo), "f"(hi));
    return r;
}
__device__ __forceinline__ void upk2(unsigned long long v, float& lo, float& hi) {
    asm("mov.b64 {%0, %1}, %2;" : "=f"(lo), "=f"(hi) : "l"(v));
}
__device__ __forceinline__ unsigned long long ffma2(unsigned long long a,
                                                    unsigned long long b,
                                                    unsigned long long c) {
    unsigned long long d;
    asm("fma.rn.f32x2 %0, %1, %2, %3;" : "=l"(d) : "l"(a), "l"(b), "l"(c));
    return d;
}

// ---------------- small setup kernels ----------------
__global__ void k_init(int n) {
    int i = blockIdx.x * blockDim.x + threadIdx.x;
    if (i < n) { g_counts[i] = 0; g_cursor[i] = 0; }
    if (i < HID) g_pooled[i] = 0.f;
    if (i < 4) g_tcnt[i] = 0;
}

__global__ void k_count_deg(const int* __restrict__ ei, int nE) {
    int e = blockIdx.x * blockDim.x + threadIdx.x;
    if (e < nE) atomicAdd(&g_counts[ei[nE + e]], 1);
}

__global__ void k_bucket(const int* __restrict__ nt, int n) {
    int i = blockIdx.x * blockDim.x + threadIdx.x;
    if (i < n) {
        int t = nt[i];
        int s = atomicAdd(&g_tcnt[t], 1);
        g_tlist[t * NMAX + s] = i;
    }
}

__global__ void __launch_bounds__(1024) k_scan(int n) {
    __shared__ int wsum[32];
    __shared__ int carry;
    int tid = threadIdx.x, lane = tid & 31, wd = tid >> 5;
    if (tid == 0) { carry = 0; g_off[0] = 0; }
    __syncthreads();
    for (int basei = 0; basei < n; basei += 1024) {
        int i = basei + tid;
        int v = (i < n) ? g_counts[i] : 0;
        int xs = v;
#pragma unroll
        for (int d = 1; d < 32; d <<= 1) {
            int t2 = __shfl_up_sync(0xffffffffu, xs, d);
            if (lane >= d) xs += t2;
        }
        if (lane == 31) wsum[wd] = xs;
        __syncthreads();
        if (wd == 0) {
            int y = wsum[lane];
#pragma unroll
            for (int d = 1; d < 32; d <<= 1) {
                int t2 = __shfl_up_sync(0xffffffffu, y, d);
                if (lane >= d) y += t2;
            }
            wsum[lane] = y;
        }
        __syncthreads();
        int pre = (wd > 0) ? wsum[wd - 1] : 0;
        int incl = xs + pre + carry;
        if (i < n) g_off[i + 1] = incl;
        __syncthreads();
        if (tid == 1023) carry = incl;
        __syncthreads();
    }
}

__global__ void k_scatter(const int* __restrict__ ei, const int* __restrict__ et, int nE) {
    int e = blockIdx.x * blockDim.x + threadIdx.x;
    if (e >= nE) return;
    int d = ei[nE + e];
    int pos = g_off[d] + atomicAdd(&g_cursor[d], 1);
    g_csr[pos] = (ei[e] << 2) | (et[e] & 3);
}

// ---------------- typed encoder: 64 nodes of one type per block ----------------
__global__ void __launch_bounds__(128) k_encoder(
    const int* __restrict__ z, const float* __restrict__ z_embed,
    const float* __restrict__ w1, const float* __restrict__ b1,
    const float* __restrict__ w2, const float* __restrict__ b2, int n)
{
    int t = blockIdx.y;
    int cntT = g_tcnt[t];
    int base = blockIdx.x * 64;
    if (base >= cntT) return;
    int cnt = min(64, cntT - base);

    __shared__ int   nds[64];
    __shared__ int   zz[64];
    __shared__ float raw_s[64][68];   // [d][node]
    __shared__ float h_s[HID][68];    // [k][node]

    int tid = threadIdx.x;
    if (tid < 64) {
        int idx = (tid < cnt) ? tid : 0;
        int node = g_tlist[t * NMAX + base + idx];
        nds[tid] = node;
        zz[tid] = z[node] * FEAT;
    }
    __syncthreads();

#pragma unroll
    for (int it = 0; it < 32; ++it) {
        int e = tid + it * 128;
        int nn = e >> 6, d = e & 63;
        raw_s[d][nn] = z_embed[zz[nn] + d];
    }
    __syncthreads();

    int j = tid;
    const float* W1 = w1 + (size_t)t * FEAT * HID;
    float acc[64];
    float bb = b1[t * HID + j];
#pragma unroll
    for (int m = 0; m < 64; ++m) acc[m] = bb;

    for (int d = 0; d < FEAT; ++d) {
        float w = __ldg(&W1[(size_t)d * HID + j]);
        const float4* rp = (const float4*)&raw_s[d][0];
#pragma unroll
        for (int q = 0; q < 16; ++q) {
            float4 r = rp[q];
            acc[4 * q + 0] += r.x * w;
            acc[4 * q + 1] += r.y * w;
            acc[4 * q + 2] += r.z * w;
            acc[4 * q + 3] += r.w * w;
        }
    }
    // relu + transpose into h_s
#pragma unroll
    for (int q = 0; q < 16; ++q) {
        float4 v;
        v.x = fmaxf(acc[4 * q + 0], 0.f);
        v.y = fmaxf(acc[4 * q + 1], 0.f);
        v.z = fmaxf(acc[4 * q + 2], 0.f);
        v.w = fmaxf(acc[4 * q + 3], 0.f);
        *(float4*)&h_s[j][4 * q] = v;
    }
    __syncthreads();

    const float* W2 = w2 + (size_t)t * HID * HID;
    bb = b2[t * HID + j];
#pragma unroll
    for (int m = 0; m < 64; ++m) acc[m] = bb;

    for (int k = 0; k < HID; ++k) {
        float w = __ldg(&W2[(size_t)k * HID + j]);
        const float4* hp = (const float4*)&h_s[k][0];
#pragma unroll
        for (int q = 0; q < 16; ++q) {
            float4 r = hp[q];
            acc[4 * q + 0] += r.x * w;
            acc[4 * q + 1] += r.y * w;
            acc[4 * q + 2] += r.z * w;
            acc[4 * q + 3] += r.w * w;
        }
    }
#pragma unroll
    for (int nn = 0; nn < 64; ++nn)
        if (nn < cnt) g_xA[(size_t)nds[nn] * HID + j] = acc[nn];
}

// ---------------- per-node relational aggregation (warp per node) ----------------
__global__ void k_aggregate(int sel, int n) {
    int gw = (blockIdx.x * blockDim.x + threadIdx.x) >> 5;
    if (gw >= n) return;
    const float* __restrict__ x = sel ? g_xB : g_xA;
    int lane = threadIdx.x & 31;
    int s = g_off[gw], e = g_off[gw + 1];
    int deg = e - s;
    float inv = 1.f / (float)(deg >= 1 ? deg : 1);
    float4 a0 = make_float4(0, 0, 0, 0), a1 = a0, a2 = a0;
    for (int i = s; i < e; ++i) {
        int p = g_csr[i];
        const float4 v = *(const float4*)(x + (size_t)(p >> 2) * HID + lane * 4);
        int et = p & 3;
        if (et == 0) { a0.x += v.x; a0.y += v.y; a0.z += v.z; a0.w += v.w; }
        else if (et == 1) { a1.x += v.x; a1.y += v.y; a1.z += v.z; a1.w += v.w; }
        else { a2.x += v.x; a2.y += v.y; a2.z += v.z; a2.w += v.w; }
    }
    float* o = g_agg + (size_t)gw * 384 + lane * 4;
    a0.x *= inv; a0.y *= inv; a0.z *= inv; a0.w *= inv;
    a1.x *= inv; a1.y *= inv; a1.z *= inv; a1.w *= inv;
    a2.x *= inv; a2.y *= inv; a2.z *= inv; a2.w *= inv;
    *(float4*)(o)       = a0;
    *(float4*)(o + 128) = a1;
    *(float4*)(o + 256) = a2;
}

// ---------------- fused [N,512]@[512,128] GEMM + bias + LayerNorm ----------------
__global__ void __launch_bounds__(256) k_gemm_ln(
    int layer,
    const float* __restrict__ lin_w_all, const float* __restrict__ lin_b_all,
    const float* __restrict__ rel_w_all,
    const float* __restrict__ ln_g_all, const float* __restrict__ ln_b_all, int n)
{
    const float* xin  = layer ? g_xB : g_xA;
    float* xout       = layer ? g_xA : g_xB;
    const float* linW = lin_w_all + (size_t)layer * HID * HID;
    const float* relW = rel_w_all + (size_t)layer * 3 * HID * HID;
    const float* lnG  = ln_g_all + layer * HID;
    const float* lnB  = ln_b_all + layer * HID;

    __shared__ float As[32][68];
    __shared__ float Ws[32][HID];
    __shared__ float Ys[64][HID + 4];

    int tid = threadIdx.x;
    int j = tid & 127;
    int g = tid >> 7;
    int base = blockIdx.x * 64;

    float linb = lin_b_all[layer * HID + j];
    unsigned long long acc[16];
    unsigned long long initv = pk2(linb, linb);
#pragma unroll
    for (int m = 0; m < 16; ++m) acc[m] = initv;

    for (int s = 0; s < 4; ++s) {
        const float* wseg = (s == 0) ? linW : relW + (size_t)(s - 1) * HID * HID;
        const float* aseg = (s == 0) ? xin : g_agg + (s - 1) * HID;
        int astride = (s == 0) ? HID : 3 * HID;
        for (int kb = 0; kb < HID; kb += 32) {
            __syncthreads();
#pragma unroll
            for (int it = 0; it < 8; ++it) {
                int e = tid + it * 256;
                int nl = e >> 5, k = e & 31;
                int node = base + nl;
                As[k][nl] = (node < n) ? aseg[(size_t)node * astride + kb + k] : 0.f;
            }
#pragma unroll
            for (int it = 0; it < 16; ++it) {
                int e = tid + it * 256;
                int k = e >> 7, jj = e & 127;
                Ws[k][jj] = __ldg(&wseg[(size_t)(kb + k) * HID + jj]);
            }
            __syncthreads();
#pragma unroll
            for (int k = 0; k < 32; ++k) {
                float w = Ws[k][j];
                unsigned long long w2 = pk2(w, w);
                const ulonglong2* ap = (const ulonglong2*)&As[k][g * 32];
#pragma unroll
                for (int q = 0; q < 8; ++q) {
                    ulonglong2 a = ap[q];
                    acc[2 * q]     = ffma2(a.x, w2, acc[2 * q]);
                    acc[2 * q + 1] = ffma2(a.y, w2, acc[2 * q + 1]);
                }
            }
        }
    }
    __syncthreads();
#pragma unroll
    for (int m = 0; m < 16; ++m) {
        float lo, hi;
        upk2(acc[m], lo, hi);
        Ys[g * 32 + 2 * m][j]     = lo;
        Ys[g * 32 + 2 * m + 1][j] = hi;
    }
    __syncthreads();

    int lane = tid & 31, wid = tid >> 5;
    float4 g4 = *(const float4*)(lnG + lane * 4);
    float4 b4 = *(const float4*)(lnB + lane * 4);
    for (int nn = wid; nn < 64; nn += 8) {
        int node = base + nn;
        if (node >= n) break;
        float4 y = *(const float4*)&Ys[nn][lane * 4];
        float s1 = y.x + y.y + y.z + y.w;
        float s2 = y.x * y.x + y.y * y.y + y.z * y.z + y.w * y.w;
#pragma unroll
        for (int o = 16; o; o >>= 1) {
            s1 += __shfl_xor_sync(0xffffffffu, s1, o);
            s2 += __shfl_xor_sync(0xffffffffu, s2, o);
        }
        float mu = s1 * (1.f / 128.f);
        float var = s2 * (1.f / 128.f) - mu * mu;
        float rs = rsqrtf(var + 1e-5f);
        float4 o4;
        o4.x = (y.x - mu) * rs * g4.x + b4.x;
        o4.y = (y.y - mu) * rs * g4.y + b4.y;
        o4.z = (y.z - mu) * rs * g4.z + b4.z;
        o4.w = (y.w - mu) * rs * g4.w + b4.w;
        *(float4*)&xout[(size_t)node * HID + lane * 4] = o4;
    }
}

// ---------------- pooling + regression head ----------------
__global__ void k_pool(int n) {
    int j = threadIdx.x & 127;
    int h = threadIdx.x >> 7;
    float s = 0.f;
    for (int node = blockIdx.x * 2 + h; node < n; node += gridDim.x * 2)
        s += g_xA[(size_t)node * HID + j];
    atomicAdd(&g_pooled[j], s);
}

__global__ void k_final(const float* __restrict__ reg_w, const float* __restrict__ reg_b,
                        float* __restrict__ out, int n) {
    int tid = threadIdx.x;
    float v = g_pooled[tid] * (1.f / (float)n) * reg_w[tid];
#pragma unroll
    for (int o = 16; o; o >>= 1) v += __shfl_xor_sync(0xffffffffu, v, o);
    __shared__ float r[4];
    if ((tid & 31) == 0) r[tid >> 5] = v;
    __syncthreads();
    if (tid == 0) out[0] = r[0] + r[1] + r[2] + r[3] + reg_b[0];
}

// ---------------- launch ----------------
extern "C" void kernel_launch(void* const* d_in, const int* in_sizes, int n_in,
                              void* d_out, int out_size) {
    const int*   z          = (const int*)d_in[0];
    const int*   node_type  = (const int*)d_in[1];
    const int*   edge_index = (const int*)d_in[2];
    const int*   edge_type  = (const int*)d_in[3];
    const float* z_embed    = (const float*)d_in[4];
    const float* enc_w1     = (const float*)d_in[5];
    const float* enc_b1     = (const float*)d_in[6];
    const float* enc_w2     = (const float*)d_in[7];
    const float* enc_b2     = (const float*)d_in[8];
    const float* lin_w      = (const float*)d_in[9];
    const float* lin_b      = (const float*)d_in[10];
    const float* rel_w      = (const float*)d_in[11];
    const float* ln_g       = (const float*)d_in[12];
    const float* ln_b       = (const float*)d_in[13];
    const float* reg_w      = (const float*)d_in[14];
    const float* reg_b      = (const float*)d_in[15];
    float* out = (float*)d_out;

    int n = in_sizes[0];
    int E = in_sizes[3];

    k_init<<<(n + 255) / 256, 256>>>(n);
    k_count_deg<<<(E + 255) / 256, 256>>>(edge_index, E);
    k_bucket<<<(n + 255) / 256, 256>>>(node_type, n);
    k_scan<<<1, 1024>>>(n);
    k_scatter<<<(E + 255) / 256, 256>>>(edge_index, edge_type, E);

    dim3 egrid((n + 63) / 64, 4);
    k_encoder<<<egrid, 128>>>(z, z_embed, enc_w1, enc_b1, enc_w2, enc_b2, n);

    int agrid = (n * 32 + 255) / 256;
    k_aggregate<<<agrid, 256>>>(0, n);
    k_gemm_ln<<<(n + 63) / 64, 256>>>(0, lin_w, lin_b, rel_w, ln_g, ln_b, n);
    k_aggregate<<<agrid, 256>>>(1, n);
    k_gemm_ln<<<(n + 63) / 64, 256>>>(1, lin_w, lin_b, rel_w, ln_g, ln_b, n);

    k_pool<<<128, 256>>>(n);
    k_final<<<1, 128>>>(reg_w, reg_b, out, n);
}

// round 2
// speedup vs baseline: 1.1097x; 1.1097x over previous
#include <cuda_runtime.h>
#include <stdint.h>

#define NMAX 50000
#define EMAX 800000
#define HID 128
#define FEAT 64

// ---------------- scratch (static device globals; no allocation) ----------------
__device__ float g_xA[(size_t)NMAX * HID];
__device__ float g_xB[(size_t)NMAX * HID];
__device__ float g_agg[(size_t)NMAX * 3 * HID];   // [node][rel][128], pre-scaled by 1/deg
__device__ int   g_counts[NMAX];
__device__ int   g_off[NMAX + 1];
__device__ int   g_cursor[NMAX];
__device__ int   g_csr[EMAX];                      // packed: (src<<2)|etype
__device__ int   g_tcnt[4];
__device__ int   g_tlist[4 * NMAX];
__device__ float g_pooled[HID];
__device__ int   g_bsum[64];
__device__ int   g_bpre[64];

// ---------------- f32x2 packed helpers (Blackwell) ----------------
__device__ __forceinline__ unsigned long long pk2(float lo, float hi) {
    unsigned long long r;
    asm("mov.b64 %0, {%1, %2};" : "=l"(r) : "f"(lo), "f"(hi));
    return r;
}
__device__ __forceinline__ void upk2(unsigned long long v, float& lo, float& hi) {
    asm("mov.b64 {%0, %1}, %2;" : "=f"(lo), "=f"(hi) : "l"(v));
}
__device__ __forceinline__ unsigned long long ffma2(unsigned long long a,
                                                    unsigned long long b,
                                                    unsigned long long c) {
    unsigned long long d;
    asm("fma.rn.f32x2 %0, %1, %2, %3;" : "=l"(d) : "l"(a), "l"(b), "l"(c));
    return d;
}

// ---------------- small setup kernels ----------------
__global__ void k_init(int n) {
    int i = blockIdx.x * blockDim.x + threadIdx.x;
    if (i < n) { g_counts[i] = 0; g_cursor[i] = 0; }
    if (i < HID) g_pooled[i] = 0.f;
    if (i < 4) g_tcnt[i] = 0;
}

__global__ void k_count_deg(const int* __restrict__ ei, int nE) {
    int e = blockIdx.x * blockDim.x + threadIdx.x;
    if (e < nE) atomicAdd(&g_counts[ei[nE + e]], 1);
}

// type bucketing with per-block smem counters (avoids 50K atomics onto 4 addrs)
__global__ void __launch_bounds__(256) k_bucket(const int* __restrict__ nt, int n) {
    __shared__ int cnt[4];
    __shared__ int basei[4];
    __shared__ unsigned cur[4];
    int t = threadIdx.x;
    if (t < 4) { cnt[t] = 0; cur[t] = 0; }
    __syncthreads();
    int i = blockIdx.x * blockDim.x + t;
    int ty = (i < n) ? nt[i] : -1;
    if (ty >= 0) atomicAdd(&cnt[ty], 1);
    __syncthreads();
    if (t < 4) basei[t] = atomicAdd(&g_tcnt[t], cnt[t]);
    __syncthreads();
    if (ty >= 0) {
        int pos = atomicAdd(&cur[ty], 1u);
        g_tlist[ty * NMAX + basei[ty] + pos] = i;
    }
}

// ---------------- 3-phase multi-block exclusive scan of g_counts ----------------
__global__ void __launch_bounds__(256) k_scan1(int n) {
    int b = blockIdx.x, t = threadIdx.x;
    int base = b * 1024 + t * 4;
    int s = 0;
    if (base + 3 < n) {
        int4 c = *(const int4*)&g_counts[base];
        s = c.x + c.y + c.z + c.w;
    } else {
        for (int q = 0; q < 4; ++q) if (base + q < n) s += g_counts[base + q];
    }
#pragma unroll
    for (int o = 16; o; o >>= 1) s += __shfl_xor_sync(0xffffffffu, s, o);
    __shared__ int ws[8];
    if ((t & 31) == 0) ws[t >> 5] = s;
    __syncthreads();
    if (t == 0) {
        int tot = 0;
#pragma unroll
        for (int w = 0; w < 8; ++w) tot += ws[w];
        g_bsum[b] = tot;
    }
}

__global__ void k_scan2(int nb) {
    int lane = threadIdx.x;
    int carry = 0;
    for (int base = 0; base < nb; base += 32) {
        int i = base + lane;
        int v = (i < nb) ? g_bsum[i] : 0;
        int x = v;
#pragma unroll
        for (int d = 1; d < 32; d <<= 1) {
            int u = __shfl_up_sync(0xffffffffu, x, d);
            if (lane >= d) x += u;
        }
        if (i < nb) g_bpre[i] = carry + x - v;
        carry += __shfl_sync(0xffffffffu, x, 31);
    }
}

__global__ void __launch_bounds__(256) k_scan3(int n) {
    __shared__ int wsum[8];
    int b = blockIdx.x, t = threadIdx.x, lane = t & 31, w = t >> 5;
    int base = b * 1024 + t * 4;
    int v0 = 0, v1 = 0, v2 = 0, v3 = 0;
    if (base + 3 < n) {
        int4 c = *(const int4*)&g_counts[base];
        v0 = c.x; v1 = c.y; v2 = c.z; v3 = c.w;
    } else {
        if (base < n) v0 = g_counts[base];
        if (base + 1 < n) v1 = g_counts[base + 1];
        if (base + 2 < n) v2 = g_counts[base + 2];
        if (base + 3 < n) v3 = g_counts[base + 3];
    }
    int s = v0 + v1 + v2 + v3;
    int x = s;
#pragma unroll
    for (int d = 1; d < 32; d <<= 1) {
        int u = __shfl_up_sync(0xffffffffu, x, d);
        if (lane >= d) x += u;
    }
    if (lane == 31) wsum[w] = x;
    __syncthreads();
    if (t == 0) {
        int run = 0;
#pragma unroll
        for (int q = 0; q < 8; ++q) { int tmp = wsum[q]; wsum[q] = run; run += tmp; }
    }
    __syncthreads();
    int pre = g_bpre[b] + wsum[w] + (x - s);
    int r = pre;
    r += v0; if (base < n)     g_off[base + 1] = r;
    r += v1; if (base + 1 < n) g_off[base + 2] = r;
    r += v2; if (base + 2 < n) g_off[base + 3] = r;
    r += v3; if (base + 3 < n) g_off[base + 4] = r;
    if (b == 0 && t == 0) g_off[0] = 0;
}

__global__ void k_scatter(const int* __restrict__ ei, const int* __restrict__ et, int nE) {
    int e = blockIdx.x * blockDim.x + threadIdx.x;
    if (e >= nE) return;
    int d = ei[nE + e];
    int pos = g_off[d] + atomicAdd(&g_cursor[d], 1);
    g_csr[pos] = (ei[e] << 2) | (et[e] & 3);
}

// ---------------- typed encoder: 64 nodes of one type per block, f32x2 packed ----------------
__global__ void __launch_bounds__(128) k_encoder(
    const int* __restrict__ z, const float* __restrict__ z_embed,
    const float* __restrict__ w1, const float* __restrict__ b1,
    const float* __restrict__ w2, const float* __restrict__ b2, int n)
{
    int t = blockIdx.y;
    int cntT = g_tcnt[t];
    int base = blockIdx.x * 64;
    if (base >= cntT) return;
    int cnt = min(64, cntT - base);

    __shared__ int   nds[64];
    __shared__ int   zz[64];
    __shared__ float raw_s[64][68];   // [d][node]
    __shared__ float h_s[HID][68];    // [k][node]

    int tid = threadIdx.x;
    if (tid < 64) {
        int idx = (tid < cnt) ? tid : 0;
        int node = g_tlist[t * NMAX + base + idx];
        nds[tid] = node;
        zz[tid] = z[node] * FEAT;
    }
    __syncthreads();

#pragma unroll
    for (int it = 0; it < 32; ++it) {
        int e = tid + it * 128;
        int nn = e >> 6, d = e & 63;
        raw_s[d][nn] = z_embed[zz[nn] + d];
    }
    __syncthreads();

    int j = tid;
    const float* W1 = w1 + (size_t)t * FEAT * HID;
    unsigned long long acc[32];
    {
        float bb = b1[t * HID + j];
        unsigned long long bb2 = pk2(bb, bb);
#pragma unroll
        for (int m = 0; m < 32; ++m) acc[m] = bb2;
    }

    for (int d = 0; d < FEAT; ++d) {
        float w = __ldg(&W1[(size_t)d * HID + j]);
        unsigned long long w2 = pk2(w, w);
        const ulonglong2* rp = (const ulonglong2*)&raw_s[d][0];
#pragma unroll
        for (int q = 0; q < 16; ++q) {
            ulonglong2 r = rp[q];
            acc[2 * q]     = ffma2(r.x, w2, acc[2 * q]);
            acc[2 * q + 1] = ffma2(r.y, w2, acc[2 * q + 1]);
        }
    }
    // relu + transpose into h_s
#pragma unroll
    for (int m = 0; m < 32; ++m) {
        float lo, hi;
        upk2(acc[m], lo, hi);
        float2 v;
        v.x = fmaxf(lo, 0.f);
        v.y = fmaxf(hi, 0.f);
        *(float2*)&h_s[j][2 * m] = v;
    }
    __syncthreads();

    const float* W2 = w2 + (size_t)t * HID * HID;
    {
        float bb = b2[t * HID + j];
        unsigned long long bb2 = pk2(bb, bb);
#pragma unroll
        for (int m = 0; m < 32; ++m) acc[m] = bb2;
    }

    for (int k = 0; k < HID; ++k) {
        float w = __ldg(&W2[(size_t)k * HID + j]);
        unsigned long long w2 = pk2(w, w);
        const ulonglong2* hp = (const ulonglong2*)&h_s[k][0];
#pragma unroll
        for (int q = 0; q < 16; ++q) {
            ulonglong2 r = hp[q];
            acc[2 * q]     = ffma2(r.x, w2, acc[2 * q]);
            acc[2 * q + 1] = ffma2(r.y, w2, acc[2 * q + 1]);
        }
    }
#pragma unroll
    for (int m = 0; m < 32; ++m) {
        float lo, hi;
        upk2(acc[m], lo, hi);
        if (2 * m < cnt)     g_xA[(size_t)nds[2 * m] * HID + j] = lo;
        if (2 * m + 1 < cnt) g_xA[(size_t)nds[2 * m + 1] * HID + j] = hi;
    }
}

// ---------------- per-node relational aggregation (warp per node, MLP=4) ----------------
__device__ __forceinline__ void acc4(float4& a, const float4& v) {
    a.x += v.x; a.y += v.y; a.z += v.z; a.w += v.w;
}

__global__ void k_aggregate(int sel, int n) {
    int gw = (blockIdx.x * blockDim.x + threadIdx.x) >> 5;
    if (gw >= n) return;
    const float* __restrict__ x = sel ? g_xB : g_xA;
    int lane = threadIdx.x & 31;
    int s = g_off[gw], e = g_off[gw + 1];
    int deg = e - s;
    float inv = 1.f / (float)(deg >= 1 ? deg : 1);
    float4 a0 = make_float4(0, 0, 0, 0), a1 = a0, a2 = a0;
    int lo4 = lane * 4;
    int i = s;
    for (; i + 4 <= e; i += 4) {
        int p0 = g_csr[i], p1 = g_csr[i + 1], p2 = g_csr[i + 2], p3 = g_csr[i + 3];
        float4 v0 = *(const float4*)(x + (size_t)(p0 >> 2) * HID + lo4);
        float4 v1 = *(const float4*)(x + (size_t)(p1 >> 2) * HID + lo4);
        float4 v2 = *(const float4*)(x + (size_t)(p2 >> 2) * HID + lo4);
        float4 v3 = *(const float4*)(x + (size_t)(p3 >> 2) * HID + lo4);
        int e0 = p0 & 3;
        if (e0 == 0) acc4(a0, v0); else if (e0 == 1) acc4(a1, v0); else acc4(a2, v0);
        int e1 = p1 & 3;
        if (e1 == 0) acc4(a0, v1); else if (e1 == 1) acc4(a1, v1); else acc4(a2, v1);
        int e2 = p2 & 3;
        if (e2 == 0) acc4(a0, v2); else if (e2 == 1) acc4(a1, v2); else acc4(a2, v2);
        int e3 = p3 & 3;
        if (e3 == 0) acc4(a0, v3); else if (e3 == 1) acc4(a1, v3); else acc4(a2, v3);
    }
    for (; i < e; ++i) {
        int p = g_csr[i];
        float4 v = *(const float4*)(x + (size_t)(p >> 2) * HID + lo4);
        int et = p & 3;
        if (et == 0) acc4(a0, v); else if (et == 1) acc4(a1, v); else acc4(a2, v);
    }
    float* o = g_agg + (size_t)gw * 384 + lo4;
    a0.x *= inv; a0.y *= inv; a0.z *= inv; a0.w *= inv;
    a1.x *= inv; a1.y *= inv; a1.z *= inv; a1.w *= inv;
    a2.x *= inv; a2.y *= inv; a2.z *= inv; a2.w *= inv;
    *(float4*)(o)       = a0;
    *(float4*)(o + 128) = a1;
    *(float4*)(o + 256) = a2;
}

// ---------------- fused [N,512]@[512,128] GEMM + bias + LayerNorm ----------------
__global__ void __launch_bounds__(256) k_gemm_ln(
    int layer,
    const float* __restrict__ lin_w_all, const float* __restrict__ lin_b_all,
    const float* __restrict__ rel_w_all,
    const float* __restrict__ ln_g_all, const float* __restrict__ ln_b_all, int n)
{
    const float* xin  = layer ? g_xB : g_xA;
    float* xout       = layer ? g_xA : g_xB;
    const float* linW = lin_w_all + (size_t)layer * HID * HID;
    const float* relW = rel_w_all + (size_t)layer * 3 * HID * HID;
    const float* lnG  = ln_g_all + layer * HID;
    const float* lnB  = ln_b_all + layer * HID;

    __shared__ float As[32][68];
    __shared__ float Ws[32][HID];
    __shared__ float Ys[64][HID + 4];

    int tid = threadIdx.x;
    int j = tid & 127;
    int g = tid >> 7;
    int base = blockIdx.x * 64;

    float linb = lin_b_all[layer * HID + j];
    unsigned long long acc[16];
    unsigned long long initv = pk2(linb, linb);
#pragma unroll
    for (int m = 0; m < 16; ++m) acc[m] = initv;

    for (int s = 0; s < 4; ++s) {
        const float* wseg = (s == 0) ? linW : relW + (size_t)(s - 1) * HID * HID;
        const float* aseg = (s == 0) ? xin : g_agg + (s - 1) * HID;
        int astride = (s == 0) ? HID : 3 * HID;
        for (int kb = 0; kb < HID; kb += 32) {
            __syncthreads();
#pragma unroll
            for (int it = 0; it < 8; ++it) {
                int e = tid + it * 256;
                int nl = e >> 5, k = e & 31;
                int node = base + nl;
                As[k][nl] = (node < n) ? aseg[(size_t)node * astride + kb + k] : 0.f;
            }
#pragma unroll
            for (int it = 0; it < 16; ++it) {
                int e = tid + it * 256;
                int k = e >> 7, jj = e & 127;
                Ws[k][jj] = __ldg(&wseg[(size_t)(kb + k) * HID + jj]);
            }
            __syncthreads();
#pragma unroll
            for (int k = 0; k < 32; ++k) {
                float w = Ws[k][j];
                unsigned long long w2 = pk2(w, w);
                const ulonglong2* ap = (const ulonglong2*)&As[k][g * 32];
#pragma unroll
                for (int q = 0; q < 8; ++q) {
                    ulonglong2 a = ap[q];
                    acc[2 * q]     = ffma2(a.x, w2, acc[2 * q]);
                    acc[2 * q + 1] = ffma2(a.y, w2, acc[2 * q + 1]);
                }
            }
        }
    }
    __syncthreads();
#pragma unroll
    for (int m = 0; m < 16; ++m) {
        float lo, hi;
        upk2(acc[m], lo, hi);
        Ys[g * 32 + 2 * m][j]     = lo;
        Ys[g * 32 + 2 * m + 1][j] = hi;
    }
    __syncthreads();

    int lane = tid & 31, wid = tid >> 5;
    float4 g4 = *(const float4*)(lnG + lane * 4);
    float4 b4 = *(const float4*)(lnB + lane * 4);
    for (int nn = wid; nn < 64; nn += 8) {
        int node = base + nn;
        if (node >= n) break;
        float4 y = *(const float4*)&Ys[nn][lane * 4];
        float s1 = y.x + y.y + y.z + y.w;
        float s2 = y.x * y.x + y.y * y.y + y.z * y.z + y.w * y.w;
#pragma unroll
        for (int o = 16; o; o >>= 1) {
            s1 += __shfl_xor_sync(0xffffffffu, s1, o);
            s2 += __shfl_xor_sync(0xffffffffu, s2, o);
        }
        float mu = s1 * (1.f / 128.f);
        float var = s2 * (1.f / 128.f) - mu * mu;
        float rs = rsqrtf(var + 1e-5f);
        float4 o4;
        o4.x = (y.x - mu) * rs * g4.x + b4.x;
        o4.y = (y.y - mu) * rs * g4.y + b4.y;
        o4.z = (y.z - mu) * rs * g4.z + b4.z;
        o4.w = (y.w - mu) * rs * g4.w + b4.w;
        *(float4*)&xout[(size_t)node * HID + lane * 4] = o4;
    }
}

// ---------------- pooling + regression head ----------------
__global__ void k_pool(int n) {
    int j = threadIdx.x & 127;
    int h = threadIdx.x >> 7;
    float s = 0.f;
    for (int node = blockIdx.x * 2 + h; node < n; node += gridDim.x * 2)
        s += g_xA[(size_t)node * HID + j];
    atomicAdd(&g_pooled[j], s);
}

__global__ void k_final(const float* __restrict__ reg_w, const float* __restrict__ reg_b,
                        float* __restrict__ out, int n) {
    int tid = threadIdx.x;
    float v = g_pooled[tid] * (1.f / (float)n) * reg_w[tid];
#pragma unroll
    for (int o = 16; o; o >>= 1) v += __shfl_xor_sync(0xffffffffu, v, o);
    __shared__ float r[4];
    if ((tid & 31) == 0) r[tid >> 5] = v;
    __syncthreads();
    if (tid == 0) out[0] = r[0] + r[1] + r[2] + r[3] + reg_b[0];
}

// ---------------- launch ----------------
extern "C" void kernel_launch(void* const* d_in, const int* in_sizes, int n_in,
                              void* d_out, int out_size) {
    const int*   z          = (const int*)d_in[0];
    const int*   node_type  = (const int*)d_in[1];
    const int*   edge_index = (const int*)d_in[2];
    const int*   edge_type  = (const int*)d_in[3];
    const float* z_embed    = (const float*)d_in[4];
    const float* enc_w1     = (const float*)d_in[5];
    const float* enc_b1     = (const float*)d_in[6];
    const float* enc_w2     = (const float*)d_in[7];
    const float* enc_b2     = (const float*)d_in[8];
    const float* lin_w      = (const float*)d_in[9];
    const float* lin_b      = (const float*)d_in[10];
    const float* rel_w      = (const float*)d_in[11];
    const float* ln_g       = (const float*)d_in[12];
    const float* ln_b       = (const float*)d_in[13];
    const float* reg_w      = (const float*)d_in[14];
    const float* reg_b      = (const float*)d_in[15];
    float* out = (float*)d_out;

    int n = in_sizes[0];
    int E = in_sizes[3];
    int nb = (n + 1023) / 1024;

    k_init<<<(n + 255) / 256, 256>>>(n);
    k_count_deg<<<(E + 255) / 256, 256>>>(edge_index, E);
    k_bucket<<<(n + 255) / 256, 256>>>(node_type, n);
    k_scan1<<<nb, 256>>>(n);
    k_scan2<<<1, 32>>>(nb);
    k_scan3<<<nb, 256>>>(n);
    k_scatter<<<(E + 255) / 256, 256>>>(edge_index, edge_type, E);

    dim3 egrid((n + 63) / 64, 4);
    k_encoder<<<egrid, 128>>>(z, z_embed, enc_w1, enc_b1, enc_w2, enc_b2, n);

    int agrid = (n * 32 + 255) / 256;
    k_aggregate<<<agrid, 256>>>(0, n);
    k_gemm_ln<<<(n + 63) / 64, 256>>>(0, lin_w, lin_b, rel_w, ln_g, ln_b, n);
    k_aggregate<<<agrid, 256>>>(1, n);
    k_gemm_ln<<<(n + 63) / 64, 256>>>(1, lin_w, lin_b, rel_w, ln_g, ln_b, n);

    k_pool<<<128, 256>>>(n);
    k_final<<<1, 128>>>(reg_w, reg_b, out, n);
}